// round 9
// baseline (speedup 1.0000x reference)
#include <cuda_runtime.h>
#include <math.h>
#include <stdint.h>

// Problem constants (match reference setup_inputs)
#define DIMF     2048
#define KIDS     8
#define P        256
#define HALF     2048
#define MARGIN   1.0f

#define THREADS  256
#define GROUP    16                    // rows per identity (2*K)
#define KSLAB    256                   // k floats per warp (8 warps x 256 = 2048)

// D(16x8) += A(16x8) * B(8x8), tf32. Gram trick: B fragments are A fragments.
#define MMA_TF32(d, a0, a1, a2, a3, b0, b1)                                \
    asm volatile(                                                          \
        "mma.sync.aligned.m16n8k8.row.col.f32.tf32.tf32.f32 "              \
        "{%0,%1,%2,%3}, {%4,%5,%6,%7}, {%8,%9}, {%0,%1,%2,%3};"            \
        : "+f"(d[0]), "+f"(d[1]), "+f"(d[2]), "+f"(d[3])                   \
        : "r"(a0), "r"(a1), "r"(a2), "r"(a3), "r"(b0), "r"(b1))

__global__ __launch_bounds__(THREADS, 2)
void wloss_kernel(const float* __restrict__ x, float* __restrict__ out)
{
    __shared__ float gram[GROUP][GROUP];

    const int p    = blockIdx.x;                 // identity
    const int tid  = threadIdx.x;
    const int w    = tid >> 5;                   // warp 0..7 (k split)
    const int lane = tid & 31;

    if (tid < GROUP * GROUP)
        gram[tid >> 4][tid & 15] = 0.0f;

    // mma.m16n8k8 tf32 A-fragment layout maps directly to row-major GMEM:
    //   a0 = X[row = lane>>2        ][k = base + (lane&3)    ]
    //   a2 = X[row = lane>>2        ][k = base + (lane&3) + 4]
    //   a1 = X[row = (lane>>2) + 8  ][k ...                  ]  (second half)
    const int fr = lane >> 2;                    // fragment row 0..7
    const int ft = lane & 3;                     // fragment k 0..3

    const float* r0 = x + (size_t)(p * KIDS + fr) * DIMF        + w * KSLAB + ft;
    const float* r1 = x + (size_t)(HALF + p * KIDS + fr) * DIMF + w * KSLAB + ft;

    float d1[4] = {0.f, 0.f, 0.f, 0.f};          // cols 0..7  (first half)
    float d2[4] = {0.f, 0.f, 0.f, 0.f};          // cols 8..15 (second half)

    // 32 k-steps of 8 over this warp's 256-float slab; no smem, no barriers.
    #pragma unroll 8
    for (int s = 0; s < KSLAB / 8; s++) {
        uint32_t a0 = __float_as_uint(__ldg(r0 + s * 8));
        uint32_t a2 = __float_as_uint(__ldg(r0 + s * 8 + 4));
        uint32_t a1 = __float_as_uint(__ldg(r1 + s * 8));
        uint32_t a3 = __float_as_uint(__ldg(r1 + s * 8 + 4));
        MMA_TF32(d1, a0, a1, a2, a3, a0, a2);    // B = rows 0..7
        MMA_TF32(d2, a0, a1, a2, a3, a1, a3);    // B = rows 8..15
    }

    // ---- reduce 8 warps' partial grams into smem ----
    {
        const int rr = lane >> 2;
        const int cc = 2 * (lane & 3);
        atomicAdd(&gram[rr][cc],             d1[0]);
        atomicAdd(&gram[rr][cc + 1],         d1[1]);
        atomicAdd(&gram[rr + 8][cc],         d1[2]);
        atomicAdd(&gram[rr + 8][cc + 1],     d1[3]);
        atomicAdd(&gram[rr][8 + cc],         d2[0]);
        atomicAdd(&gram[rr][8 + cc + 1],     d2[1]);
        atomicAdd(&gram[rr + 8][8 + cc],     d2[2]);
        atomicAdd(&gram[rr + 8][8 + cc + 1], d2[3]);
    }
    __syncthreads();

    // ---- mins + loss (warp 0; diag of gram == squared norms) ----
    if (w == 0) {
        const int r = lane & 15;
        float inv = 1.0f / (sqrtf(gram[r][r]) + 1e-10f);
        float minf = INFINITY, mins = INFINITY;
        #pragma unroll
        for (int c = 0; c < GROUP; c++) {
            float invc = __shfl_sync(0xffffffffu, inv, c);
            float v = gram[r][c] * inv * invc;
            if (c < KIDS) minf = fminf(minf, v);
            else          mins = fminf(mins, v);
        }
        float li = fmaxf(MARGIN - minf, 0.0f) + fmaxf(MARGIN - mins, 0.0f);
        if (lane >= 16) li = 0.0f;
        #pragma unroll
        for (int o = 16; o; o >>= 1)
            li += __shfl_xor_sync(0xffffffffu, li, o);
        if (lane == 0)
            atomicAdd(out, li);
    }
}

extern "C" void kernel_launch(void* const* d_in, const int* in_sizes, int n_in,
                              void* d_out, int out_size)
{
    const float* x = (const float*)d_in[0];
    float* out = (float*)d_out;

    cudaMemsetAsync(out, 0, sizeof(float), 0);
    wloss_kernel<<<P, THREADS>>>(x, out);
}

// round 10
// speedup vs baseline: 1.0875x; 1.0875x over previous
#include <cuda_runtime.h>
#include <math.h>
#include <stdint.h>

// Problem constants (match reference setup_inputs)
#define DIMF     2048
#define KIDS     8
#define P        256
#define HALF     2048
#define MARGIN   1.0f

#define GRID     512                   // 256 identities x 2 K-halves
#define THREADS  256
#define GROUP    16                    // rows per identity (2*K)
#define KH       1024                  // K floats per CTA (half of DIMF)
#define CHUNK    256                   // K floats per chunk
#define NCHUNK   (KH / CHUNK)          // 4
#define STRIDE_F 260                   // padded smem row stride (floats)
#define ROW_BYTES    (CHUNK * 4)       // 1024 B per row per chunk
#define STRIDE_BYTES (STRIDE_F * 4)    // 1040 (16B multiple)
#define BUF_FLOATS   (GROUP * STRIDE_F)
#define BUF_BYTES    (GROUP * STRIDE_BYTES)   // 16640
#define SMEM_BYTES   (2 * BUF_BYTES)          // 33280

// D(16x8) += A(16x8) * B(8x8), tf32. Gram trick: B fragments are A fragments.
#define MMA_TF32(d, a0, a1, a2, a3, b0, b1)                                \
    asm volatile(                                                          \
        "mma.sync.aligned.m16n8k8.row.col.f32.tf32.tf32.f32 "              \
        "{%0,%1,%2,%3}, {%4,%5,%6,%7}, {%8,%9}, {%0,%1,%2,%3};"            \
        : "+f"(d[0]), "+f"(d[1]), "+f"(d[2]), "+f"(d[3])                   \
        : "r"(a0), "r"(a1), "r"(a2), "r"(a3), "r"(b0), "r"(b1))

__device__ float g_gram[P][GROUP * GROUP];
__device__ int   g_cnt[P];

__device__ __forceinline__ uint32_t smem_u32(const void* p) {
    return (uint32_t)__cvta_generic_to_shared(p);
}
__device__ __forceinline__ void mbar_wait(uint32_t mbar, uint32_t parity) {
    asm volatile(
        "{\n\t.reg .pred P1;\n\t"
        "LAB_WAIT_%=:\n\t"
        "mbarrier.try_wait.parity.acquire.cta.shared::cta.b64 P1, [%0], %1, 0x989680;\n\t"
        "@P1 bra.uni LAB_DONE_%=;\n\t"
        "bra.uni LAB_WAIT_%=;\n\t"
        "LAB_DONE_%=:\n\t}"
        :: "r"(mbar), "r"(parity) : "memory");
}

__global__ __launch_bounds__(THREADS, 4)
void wloss_kernel(const float* __restrict__ x, float* __restrict__ out)
{
    extern __shared__ float smf[];               // [2][16][STRIDE_F]
    __shared__ float    gram[GROUP][GROUP];
    __shared__ uint64_t s_mbar[2];
    __shared__ int      s_last;

    const int tid  = threadIdx.x;
    const int w    = tid >> 5;                   // warp 0..7 (k split)
    const int lane = tid & 31;
    const int pg   = blockIdx.x >> 1;            // identity
    const int ks   = blockIdx.x & 1;             // K half

    const uint32_t smbase = smem_u32(smf);
    const uint32_t mbb    = smem_u32(&s_mbar[0]);

    ((float*)gram)[tid] = 0.0f;
    if (tid == 0) {
        asm volatile("mbarrier.init.shared.b64 [%0], 1;" :: "r"(mbb)      : "memory");
        asm volatile("mbarrier.init.shared.b64 [%0], 1;" :: "r"(mbb + 8u) : "memory");
    }
    __syncthreads();

    // ---- bulk-async staging: 16 rows x 1KB per chunk, mbarrier-tracked ----
    auto stage = [&](int ch, int b) {
        uint32_t mb = mbb + 8u * b;
        asm volatile("mbarrier.arrive.expect_tx.shared.b64 _, [%0], %1;"
                     :: "r"(mb), "r"((uint32_t)(GROUP * ROW_BYTES)) : "memory");
        #pragma unroll
        for (int r = 0; r < GROUP; r++) {
            int grow = (r < KIDS) ? (pg * KIDS + r)
                                  : (HALF + pg * KIDS + (r - KIDS));
            const float* src = x + (size_t)grow * DIMF + ks * KH + ch * CHUNK;
            uint32_t dst = smbase + (uint32_t)(b * BUF_BYTES + r * STRIDE_BYTES);
            asm volatile(
                "cp.async.bulk.shared::cluster.global.mbarrier::complete_tx::bytes "
                "[%0], [%1], %2, [%3];"
                :: "r"(dst), "l"(src), "r"((uint32_t)ROW_BYTES), "r"(mb)
                : "memory");
        }
    };

    if (tid == 0) { stage(0, 0); stage(1, 1); }

    // ---- main loop: warp w handles 32-float k-slab of each chunk ----
    float d1[4] = {0.f, 0.f, 0.f, 0.f};          // cols 0..7
    float d2[4] = {0.f, 0.f, 0.f, 0.f};          // cols 8..15
    const int fr = lane >> 2;                    // fragment row 0..7
    const int ft = lane & 3;                     // fragment k 0..3

    #pragma unroll
    for (int ch = 0; ch < NCHUNK; ch++) {
        const int b = ch & 1;
        mbar_wait(mbb + 8u * b, (uint32_t)((ch >> 1) & 1));

        const float* b0p = smf + b * BUF_FLOATS + fr * STRIDE_F + w * 32 + ft;
        const float* b1p = b0p + 8 * STRIDE_F;
        #pragma unroll
        for (int s = 0; s < 4; s++) {
            uint32_t a0 = __float_as_uint(b0p[s * 8]);
            uint32_t a2 = __float_as_uint(b0p[s * 8 + 4]);
            uint32_t a1 = __float_as_uint(b1p[s * 8]);
            uint32_t a3 = __float_as_uint(b1p[s * 8 + 4]);
            MMA_TF32(d1, a0, a1, a2, a3, a0, a2);   // B = rows 0..7
            MMA_TF32(d2, a0, a1, a2, a3, a1, a3);   // B = rows 8..15
        }
        if (ch + 2 < NCHUNK) {
            __syncthreads();                     // all warps done with buffer b
            if (tid == 0) stage(ch + 2, b);
        }
    }

    // ---- reduce 8 warps' partial grams into smem ----
    {
        const int rr = lane >> 2;
        const int cc = 2 * (lane & 3);
        atomicAdd(&gram[rr][cc],             d1[0]);
        atomicAdd(&gram[rr][cc + 1],         d1[1]);
        atomicAdd(&gram[rr + 8][cc],         d1[2]);
        atomicAdd(&gram[rr + 8][cc + 1],     d1[3]);
        atomicAdd(&gram[rr][8 + cc],         d2[0]);
        atomicAdd(&gram[rr][8 + cc + 1],     d2[1]);
        atomicAdd(&gram[rr + 8][8 + cc],     d2[2]);
        atomicAdd(&gram[rr + 8][8 + cc + 1], d2[3]);
    }
    __syncthreads();

    // ---- merge CTA partial into global gram, elect last CTA ----
    atomicAdd(&g_gram[pg][tid], ((float*)gram)[tid]);
    __threadfence();
    __syncthreads();
    if (tid == 0) {
        int v = atomicAdd(&g_cnt[pg], 1);
        s_last = (v == 1);
    }
    __syncthreads();
    if (!s_last) return;

    // ---- last CTA: load merged gram, reset scratch, compute loss ----
    __threadfence();
    float gv = __ldcg(&g_gram[pg][tid]);
    ((float*)gram)[tid] = gv;
    g_gram[pg][tid] = 0.0f;                      // reset for next replay
    if (tid == 0) g_cnt[pg] = 0;
    __syncthreads();

    if (w == 0) {
        const int r = lane & 15;
        float inv = 1.0f / (sqrtf(gram[r][r]) + 1e-10f);
        float minf = INFINITY, mins = INFINITY;
        #pragma unroll
        for (int c = 0; c < GROUP; c++) {
            float invc = __shfl_sync(0xffffffffu, inv, c);
            float v = gram[r][c] * inv * invc;
            if (c < KIDS) minf = fminf(minf, v);
            else          mins = fminf(mins, v);
        }
        float li = fmaxf(MARGIN - minf, 0.0f) + fmaxf(MARGIN - mins, 0.0f);
        if (lane >= 16) li = 0.0f;
        #pragma unroll
        for (int o = 16; o; o >>= 1)
            li += __shfl_xor_sync(0xffffffffu, li, o);
        if (lane == 0)
            atomicAdd(out, li);
    }
}

extern "C" void kernel_launch(void* const* d_in, const int* in_sizes, int n_in,
                              void* d_out, int out_size)
{
    const float* x = (const float*)d_in[0];
    float* out = (float*)d_out;

    cudaMemsetAsync(out, 0, sizeof(float), 0);

    static bool attr_set = false;
    if (!attr_set) {
        cudaFuncSetAttribute(wloss_kernel,
                             cudaFuncAttributeMaxDynamicSharedMemorySize,
                             SMEM_BYTES);
        attr_set = true;
    }

    wloss_kernel<<<GRID, THREADS, SMEM_BYTES>>>(x, out);
}

// round 11
// speedup vs baseline: 1.4471x; 1.3307x over previous
#include <cuda_runtime.h>
#include <math.h>
#include <stdint.h>

// Problem constants (match reference setup_inputs)
#define DIMF     2048
#define KIDS     8
#define P        256
#define HALF     2048
#define MARGIN   1.0f

#define THREADS  256
#define GROUP    16                    // rows per identity (2*K)
#define WARPS    8
#define KSLAB    256                   // k floats per warp
#define TILEK    128                   // k floats per tile
#define NTILE    (KSLAB / TILEK)       // 2
#define SROW_F   132                   // padded smem row stride (floats); 33 f4
#define WARP_SMEM_F (GROUP * SROW_F)   // 2112 floats = 8448 B per warp
#define SMEM_BYTES  (WARPS * WARP_SMEM_F * 4)   // 67584 B

// D(16x8) += A(16x8) * B(8x8), tf32. Gram trick: B fragments are A fragments.
#define MMA_TF32(d, a0, a1, a2, a3, b0, b1)                                \
    asm volatile(                                                          \
        "mma.sync.aligned.m16n8k8.row.col.f32.tf32.tf32.f32 "              \
        "{%0,%1,%2,%3}, {%4,%5,%6,%7}, {%8,%9}, {%0,%1,%2,%3};"            \
        : "+f"(d[0]), "+f"(d[1]), "+f"(d[2]), "+f"(d[3])                   \
        : "r"(a0), "r"(a1), "r"(a2), "r"(a3), "r"(b0), "r"(b1))

__global__ __launch_bounds__(THREADS, 2)
void wloss_kernel(const float* __restrict__ x, float* __restrict__ out)
{
    extern __shared__ float smf[];               // [8 warps][16][SROW_F]
    __shared__ float gram[GROUP][GROUP];

    const int p    = blockIdx.x;                 // identity
    const int tid  = threadIdx.x;
    const int w    = tid >> 5;                   // warp 0..7 (k split)
    const int lane = tid & 31;

    if (tid < GROUP * GROUP)
        gram[tid >> 4][tid & 15] = 0.0f;
    // NOTE: gram is only read after the final __syncthreads below.

    const float4* x4  = reinterpret_cast<const float4*>(x);
    float*  swm  = smf + w * WARP_SMEM_F;        // this warp's private buffer
    float4* swm4 = reinterpret_cast<float4*>(swm);

    // global float4 row bases for the 16 member rows
    // row j < 8: first half;  j >= 8: second half
    float4 r[GROUP];                             // tile staging registers

    // load tile t (16 rows x 128 floats): warp-instr j = 512B of row j
    auto ldg_tile = [&](int t) {
        const int c4 = (w * KSLAB + t * TILEK) >> 2;   // float4 k-offset
        #pragma unroll
        for (int j = 0; j < GROUP; j++) {
            int grow = (j < KIDS) ? (p * KIDS + j)
                                  : (HALF + p * KIDS + (j - KIDS));
            r[j] = x4[(size_t)grow * (DIMF / 4) + c4 + lane];
        }
    };
    // store staged tile into warp-private smem (conflict-free per phase)
    auto sts_tile = [&]() {
        #pragma unroll
        for (int j = 0; j < GROUP; j++)
            swm4[j * (SROW_F / 4) + lane] = r[j];
    };

    // MMA fragment pointers (conflict-free: bank = (4*row + col) % 32)
    const int fr = lane >> 2;                    // fragment row 0..7
    const int ft = lane & 3;                     // fragment k 0..3
    const float* b0p = swm + fr * SROW_F + ft;   // rows 0..7  (first half)
    const float* b1p = b0p + 8 * SROW_F;         // rows 8..15 (second half)

    float d1[4] = {0.f, 0.f, 0.f, 0.f};          // cols 0..7
    float d2[4] = {0.f, 0.f, 0.f, 0.f};          // cols 8..15

    auto compute_tile = [&]() {
        #pragma unroll
        for (int s = 0; s < TILEK / 8; s++) {
            uint32_t a0 = __float_as_uint(b0p[s * 8]);
            uint32_t a2 = __float_as_uint(b0p[s * 8 + 4]);
            uint32_t a1 = __float_as_uint(b1p[s * 8]);
            uint32_t a3 = __float_as_uint(b1p[s * 8 + 4]);
            MMA_TF32(d1, a0, a1, a2, a3, a0, a2);   // B = rows 0..7
            MMA_TF32(d2, a0, a1, a2, a3, a1, a3);   // B = rows 8..15
        }
    };

    // ---- per-warp pipeline: no CTA barriers, no mbarriers ----
    ldg_tile(0);
    sts_tile();
    ldg_tile(1);                 // overlaps tile-0 compute
    __syncwarp();
    compute_tile();
    __syncwarp();                // all lanes done reading tile 0
    sts_tile();
    __syncwarp();
    compute_tile();

    // ---- reduce 8 warps' partial grams into smem ----
    {
        const int rr = lane >> 2;
        const int cc = 2 * (lane & 3);
        atomicAdd(&gram[rr][cc],             d1[0]);
        atomicAdd(&gram[rr][cc + 1],         d1[1]);
        atomicAdd(&gram[rr + 8][cc],         d1[2]);
        atomicAdd(&gram[rr + 8][cc + 1],     d1[3]);
        atomicAdd(&gram[rr][8 + cc],         d2[0]);
        atomicAdd(&gram[rr][8 + cc + 1],     d2[1]);
        atomicAdd(&gram[rr + 8][8 + cc],     d2[2]);
        atomicAdd(&gram[rr + 8][8 + cc + 1], d2[3]);
    }
    __syncthreads();

    // ---- mins + loss (warp 0; diag of gram == squared norms) ----
    if (w == 0) {
        const int rr = lane & 15;
        float inv = 1.0f / (sqrtf(gram[rr][rr]) + 1e-10f);
        float minf = INFINITY, mins = INFINITY;
        #pragma unroll
        for (int c = 0; c < GROUP; c++) {
            float invc = __shfl_sync(0xffffffffu, inv, c);
            float v = gram[rr][c] * inv * invc;
            if (c < KIDS) minf = fminf(minf, v);
            else          mins = fminf(mins, v);
        }
        float li = fmaxf(MARGIN - minf, 0.0f) + fmaxf(MARGIN - mins, 0.0f);
        if (lane >= 16) li = 0.0f;
        #pragma unroll
        for (int o = 16; o; o >>= 1)
            li += __shfl_xor_sync(0xffffffffu, li, o);
        if (lane == 0)
            atomicAdd(out, li);
    }
}

extern "C" void kernel_launch(void* const* d_in, const int* in_sizes, int n_in,
                              void* d_out, int out_size)
{
    const float* x = (const float*)d_in[0];
    float* out = (float*)d_out;

    cudaMemsetAsync(out, 0, sizeof(float), 0);

    static bool attr_set = false;
    if (!attr_set) {
        cudaFuncSetAttribute(wloss_kernel,
                             cudaFuncAttributeMaxDynamicSharedMemorySize,
                             SMEM_BYTES);
        attr_set = true;
    }

    wloss_kernel<<<P, THREADS, SMEM_BYTES>>>(x, out);
}

// round 13
// speedup vs baseline: 1.4704x; 1.0161x over previous
#include <cuda_runtime.h>
#include <math.h>
#include <stdint.h>

// Problem constants (match reference setup_inputs)
#define DIMF     2048
#define KIDS     8
#define P        256
#define HALF     2048
#define MARGIN   1.0f

#define THREADS  256
#define GROUP    16                    // rows per identity (2*K)
#define CHUNK    512                   // K floats per chunk
#define CH_F4    (CHUNK / 4)           // 128
#define NCHUNK   (DIMF / CHUNK)        // 4
#define STRIDE_F 516                   // padded smem row stride (floats)
#define STRIDE_F4 (STRIDE_F / 4)       // 129
#define ROW_BYTES    (CHUNK * 4)       // 2048 B per row per chunk
#define STRIDE_BYTES (STRIDE_F * 4)    // 2064 (16B multiple)
#define BUF_FLOATS   (GROUP * STRIDE_F)
#define BUF_F4       (GROUP * STRIDE_F4)
#define BUF_BYTES    (GROUP * STRIDE_BYTES)   // 33024
#define SMEM_BYTES   (2 * BUF_BYTES)          // 66048

// D(16x8) += A(16x8) * B(8x8), tf32. Gram trick: B fragments are A fragments.
#define MMA_TF32(d, a0, a1, a2, a3, b0, b1)                                \
    asm volatile(                                                          \
        "mma.sync.aligned.m16n8k8.row.col.f32.tf32.tf32.f32 "              \
        "{%0,%1,%2,%3}, {%4,%5,%6,%7}, {%8,%9}, {%0,%1,%2,%3};"            \
        : "+f"(d[0]), "+f"(d[1]), "+f"(d[2]), "+f"(d[3])                   \
        : "r"(a0), "r"(a1), "r"(a2), "r"(a3), "r"(b0), "r"(b1))

__device__ __forceinline__ uint32_t smem_u32(const void* p) {
    return (uint32_t)__cvta_generic_to_shared(p);
}
__device__ __forceinline__ void mbar_wait(uint32_t mbar, uint32_t parity) {
    asm volatile(
        "{\n\t.reg .pred P1;\n\t"
        "LAB_WAIT_%=:\n\t"
        "mbarrier.try_wait.parity.acquire.cta.shared::cta.b64 P1, [%0], %1, 0x989680;\n\t"
        "@P1 bra.uni LAB_DONE_%=;\n\t"
        "bra.uni LAB_WAIT_%=;\n\t"
        "LAB_DONE_%=:\n\t}"
        :: "r"(mbar), "r"(parity) : "memory");
}

__global__ __launch_bounds__(THREADS, 2)
void wloss_kernel(const float* __restrict__ x, float* __restrict__ out)
{
    extern __shared__ float smf[];               // [2][16][STRIDE_F]
    float4* smf4 = reinterpret_cast<float4*>(smf);
    __shared__ float    gram[GROUP][GROUP];
    __shared__ uint64_t s_mbar;

    const int p    = blockIdx.x;                 // identity
    const int tid  = threadIdx.x;
    const int w    = tid >> 5;                   // warp 0..7 (k split)
    const int lane = tid & 31;

    const uint32_t mb = smem_u32(&s_mbar);

    if (tid < GROUP * GROUP)
        gram[tid >> 4][tid & 15] = 0.0f;
    if (tid == 0)
        asm volatile("mbarrier.init.shared.b64 [%0], 1;" :: "r"(mb) : "memory");
    __syncthreads();

    const float4* x4 = reinterpret_cast<const float4*>(x);

    // ---- path A: bulk-async staging (TMA engine), even chunks -> buf0 ----
    auto stage_bulk = [&](int ch) {
        asm volatile("mbarrier.arrive.expect_tx.shared.b64 _, [%0], %1;"
                     :: "r"(mb), "r"((uint32_t)(GROUP * ROW_BYTES)) : "memory");
        #pragma unroll
        for (int r = 0; r < GROUP; r++) {
            int grow = (r < KIDS) ? (p * KIDS + r)
                                  : (HALF + p * KIDS + (r - KIDS));
            const float* src = x + (size_t)grow * DIMF + ch * CHUNK;
            uint32_t dst = smem_u32(smf) + (uint32_t)(r * STRIDE_BYTES);
            asm volatile(
                "cp.async.bulk.shared::cluster.global.mbarrier::complete_tx::bytes "
                "[%0], [%1], %2, [%3];"
                :: "r"(dst), "l"(src), "r"((uint32_t)ROW_BYTES), "r"(mb)
                : "memory");
        }
    };

    // ---- path B: LDG.128 -> regs -> STS, odd chunks -> buf1 ----
    float4 ra[8];
    auto ldg_chunk = [&](int ch) {
        #pragma unroll
        for (int j = 0; j < 8; j++) {
            int i   = j * THREADS + tid;
            int row = i >> 7;                    // 0..15
            int c4  = i & (CH_F4 - 1);
            int grow = (row < KIDS) ? (p * KIDS + row)
                                    : (HALF + p * KIDS + (row - KIDS));
            ra[j] = __ldg(&x4[(size_t)grow * (DIMF / 4) + ch * CH_F4 + c4]);
        }
    };
    auto sts_chunk = [&]() {                     // always into buf1
        #pragma unroll
        for (int j = 0; j < 8; j++) {
            int i   = j * THREADS + tid;
            int row = i >> 7;
            int c4  = i & (CH_F4 - 1);
            smf4[BUF_F4 + row * STRIDE_F4 + c4] = ra[j];
        }
    };

    // ---- MMA compute from buffer b (0 or 1 ONLY) ----
    const int fr = lane >> 2;                    // fragment row 0..7
    const int ft = lane & 3;                     // fragment k 0..3
    float d1[4] = {0.f, 0.f, 0.f, 0.f};          // cols 0..7
    float d2[4] = {0.f, 0.f, 0.f, 0.f};          // cols 8..15

    auto compute = [&](int b) {                  // warp w: k-slab [w*64,+64)
        const float* b0p = smf + b * BUF_FLOATS + fr * STRIDE_F + w * 64 + ft;
        const float* b1p = b0p + 8 * STRIDE_F;
        #pragma unroll
        for (int s = 0; s < 8; s++) {
            uint32_t a0 = __float_as_uint(b0p[s * 8]);
            uint32_t a2 = __float_as_uint(b0p[s * 8 + 4]);
            uint32_t a1 = __float_as_uint(b1p[s * 8]);
            uint32_t a3 = __float_as_uint(b1p[s * 8 + 4]);
            MMA_TF32(d1, a0, a1, a2, a3, a0, a2);   // B = rows 0..7
            MMA_TF32(d2, a0, a1, a2, a3, a1, a3);   // B = rows 8..15
        }
    };

    // ---- dual-path pipeline ----
    // chunk 0 -> buf0 (TMA), chunk 1 -> buf1 (LDG),
    // chunk 2 -> buf0 (TMA), chunk 3 -> buf1 (LDG)
    ldg_chunk(1);                        // LSU path: chunk 1 in flight
    if (tid == 0) stage_bulk(0);         // TMA path: chunk 0 in flight

    mbar_wait(mb, 0u);                   // chunk 0 ready in buf0
    compute(0);                          // chunk 0 from buf0
    __syncthreads();                     // buf0 free; everyone has ra(ch1)

    sts_chunk();                         // chunk 1 -> buf1
    if (tid == 0) stage_bulk(2);         // TMA path: chunk 2 -> buf0
    ldg_chunk(3);                        // LSU path: chunk 3 -> regs
    __syncthreads();                     // STS visible

    compute(1);                          // chunk 1 from buf1
    mbar_wait(mb, 1u);                   // chunk 2 ready in buf0
    compute(0);                          // chunk 2 from buf0
    __syncthreads();                     // all warps done reading buf1

    sts_chunk();                         // chunk 3 -> buf1
    __syncthreads();
    compute(1);                          // chunk 3 from buf1

    // ---- reduce 8 warps' partial grams into smem ----
    {
        const int rr = lane >> 2;
        const int cc = 2 * (lane & 3);
        atomicAdd(&gram[rr][cc],             d1[0]);
        atomicAdd(&gram[rr][cc + 1],         d1[1]);
        atomicAdd(&gram[rr + 8][cc],         d1[2]);
        atomicAdd(&gram[rr + 8][cc + 1],     d1[3]);
        atomicAdd(&gram[rr][8 + cc],         d2[0]);
        atomicAdd(&gram[rr][8 + cc + 1],     d2[1]);
        atomicAdd(&gram[rr + 8][8 + cc],     d2[2]);
        atomicAdd(&gram[rr + 8][8 + cc + 1], d2[3]);
    }
    __syncthreads();

    // ---- mins + loss (warp 0; diag of gram == squared norms) ----
    if (w == 0) {
        const int r = lane & 15;
        float inv = 1.0f / (sqrtf(gram[r][r]) + 1e-10f);
        float minf = INFINITY, mins = INFINITY;
        #pragma unroll
        for (int c = 0; c < GROUP; c++) {
            float invc = __shfl_sync(0xffffffffu, inv, c);
            float v = gram[r][c] * inv * invc;
            if (c < KIDS) minf = fminf(minf, v);
            else          mins = fminf(mins, v);
        }
        float li = fmaxf(MARGIN - minf, 0.0f) + fmaxf(MARGIN - mins, 0.0f);
        if (lane >= 16) li = 0.0f;
        #pragma unroll
        for (int o = 16; o; o >>= 1)
            li += __shfl_xor_sync(0xffffffffu, li, o);
        if (lane == 0)
            atomicAdd(out, li);
    }
}

extern "C" void kernel_launch(void* const* d_in, const int* in_sizes, int n_in,
                              void* d_out, int out_size)
{
    const float* x = (const float*)d_in[0];
    float* out = (float*)d_out;

    cudaMemsetAsync(out, 0, sizeof(float), 0);

    static bool attr_set = false;
    if (!attr_set) {
        cudaFuncSetAttribute(wloss_kernel,
                             cudaFuncAttributeMaxDynamicSharedMemorySize,
                             SMEM_BYTES);
        attr_set = true;
    }

    wloss_kernel<<<P, THREADS, SMEM_BYTES>>>(x, out);
}